// round 1
// baseline (speedup 1.0000x reference)
#include <cuda_runtime.h>
#include <math.h>

// Problem constants
#define N_POS   65536          // B*H*W = 16*64*64
#define N_E     2048           // codebook entries
#define C_DIM   64             // embedding dim
#define PLANE   4096           // H*W
#define ZQ_ELEMS 4194304       // 16*64*64*64

// Persistent device scratch (no allocations allowed)
__device__ int   g_idx[N_POS];
__device__ int   g_hist[N_E];
__device__ float g_loss;

// ---------------------------------------------------------------------------
// Kernel 0: zero accumulators (must be re-zeroed on every launch for graph replay)
// ---------------------------------------------------------------------------
__global__ void vq_init_kernel() {
    int tid = threadIdx.x;
    #pragma unroll
    for (int k = tid; k < N_E; k += 256) g_hist[k] = 0;
    if (tid == 0) g_loss = 0.0f;
}

// ---------------------------------------------------------------------------
// Kernel 1: argmax GEMM.  Block = 128 positions x full 2048 codes (in 128-code
// chunks). 256 threads, each computes an 8x8 (pos x code) register tile.
// smem: z_t[64][128] (c-major positions), cb_t[64][128] (c-major codes).
// fp32 accumulation -> argmax matches the fp32 reference.
// ---------------------------------------------------------------------------
extern __shared__ float dyn_smem[];

__global__ void __launch_bounds__(256, 2)
vq_argmax_kernel(const float* __restrict__ z, const float* __restrict__ cb) {
    float* z_t  = dyn_smem;            // 64*128 floats = 32 KB
    float* cb_t = dyn_smem + 8192;     // 64*128 floats = 32 KB

    const int tid = threadIdx.x;
    const int n0  = blockIdx.x * 128;          // first position of this tile
    const int b   = n0 >> 12;                  // batch (4096 positions per batch)
    const int p0  = n0 & 4095;                 // offset within the HW plane
    const float* zb = z + (size_t)b * (C_DIM * PLANE) + p0;

    // ---- load z tile: z_t[c][pos], coalesced float4 ----
    #pragma unroll
    for (int k = 0; k < 8; k++) {
        int fid = tid + k * 256;               // 0..2047 float4 units
        int c   = fid >> 5;                    // 0..63
        int pg  = fid & 31;                    // 0..31 (pos group of 4)
        float4 v = *(const float4*)(zb + c * PLANE + pg * 4);
        *(float4*)&z_t[c * 128 + pg * 4] = v;
    }

    const int tx = tid & 15;                   // position group (8 positions)
    const int ty = tid >> 4;                   // code group     (8 codes)

    float bestv[8];
    int   besti[8];
    #pragma unroll
    for (int i = 0; i < 8; i++) { bestv[i] = -1e30f; besti[i] = 0; }

    for (int chunk = 0; chunk < N_E; chunk += 128) {
        __syncthreads();
        // ---- load codebook chunk transposed: cb_t[c][code] ----
        #pragma unroll
        for (int k = 0; k < 8; k++) {
            int fid  = tid + k * 256;          // 0..2047 float4 units
            int code = fid & 127;
            int c4   = fid >> 7;               // 0..15
            float4 v = *(const float4*)(cb + (size_t)(chunk + code) * C_DIM + c4 * 4);
            cb_t[(c4 * 4 + 0) * 128 + code] = v.x;
            cb_t[(c4 * 4 + 1) * 128 + code] = v.y;
            cb_t[(c4 * 4 + 2) * 128 + code] = v.z;
            cb_t[(c4 * 4 + 3) * 128 + code] = v.w;
        }
        __syncthreads();

        // ---- 8x8 register-tile dot products over c ----
        float acc[8][8];
        #pragma unroll
        for (int i = 0; i < 8; i++)
            #pragma unroll
            for (int j = 0; j < 8; j++) acc[i][j] = 0.0f;

        #pragma unroll 16
        for (int c = 0; c < C_DIM; c++) {
            float4 a0 = *(float4*)&z_t[c * 128 + tx * 8];
            float4 a1 = *(float4*)&z_t[c * 128 + tx * 8 + 4];
            float4 b0 = *(float4*)&cb_t[c * 128 + ty * 8];
            float4 b1 = *(float4*)&cb_t[c * 128 + ty * 8 + 4];
            float av[8] = {a0.x, a0.y, a0.z, a0.w, a1.x, a1.y, a1.z, a1.w};
            float bv[8] = {b0.x, b0.y, b0.z, b0.w, b1.x, b1.y, b1.z, b1.w};
            #pragma unroll
            for (int i = 0; i < 8; i++)
                #pragma unroll
                for (int j = 0; j < 8; j++)
                    acc[i][j] = fmaf(av[i], bv[j], acc[i][j]);
        }

        // ---- running argmax (strict > keeps the lowest index on ties,
        //      matching jnp.argmax first-occurrence semantics) ----
        #pragma unroll
        for (int j = 0; j < 8; j++) {
            int code = chunk + ty * 8 + j;
            #pragma unroll
            for (int i = 0; i < 8; i++) {
                if (acc[i][j] > bestv[i]) { bestv[i] = acc[i][j]; besti[i] = code; }
            }
        }
    }

    // ---- cross-thread reduction over the 16 code groups ----
    __syncthreads();
    float* bvs = dyn_smem;                       // [16][128]
    int*   bis = (int*)(dyn_smem + 8192);        // [16][128]
    #pragma unroll
    for (int i = 0; i < 8; i++) {
        bvs[ty * 128 + tx * 8 + i] = bestv[i];
        bis[ty * 128 + tx * 8 + i] = besti[i];
    }
    __syncthreads();
    if (tid < 128) {
        float bv0 = bvs[tid];
        int   bi0 = bis[tid];
        #pragma unroll
        for (int t = 1; t < 16; t++) {
            float v = bvs[t * 128 + tid];
            int   ii = bis[t * 128 + tid];
            if (v > bv0 || (v == bv0 && ii < bi0)) { bv0 = v; bi0 = ii; }
        }
        g_idx[n0 + tid] = bi0;
    }
}

// ---------------------------------------------------------------------------
// Kernel 2: gather codebook[idx] -> z_q (transposed back to [B,C,H,W]),
// accumulate loss sum, per-block histogram, write indices as float.
// One thread per position; 256 positions per block.
// ---------------------------------------------------------------------------
__global__ void __launch_bounds__(256)
vq_gather_kernel(const float* __restrict__ z, const float* __restrict__ cb,
                 float* __restrict__ out_zq, float* __restrict__ out_idx_f) {
    __shared__ int   sh_hist[N_E];
    __shared__ float sh_red[8];

    const int tid = threadIdx.x;
    #pragma unroll
    for (int k = tid; k < N_E; k += 256) sh_hist[k] = 0;
    __syncthreads();

    const int n = blockIdx.x * 256 + tid;
    const int e = g_idx[n];
    const int b = n >> 12;
    const int p = n & 4095;
    const float*  zb = z      + (size_t)b * (C_DIM * PLANE) + p;
    float*        ob = out_zq + (size_t)b * (C_DIM * PLANE) + p;
    const float4* cr = (const float4*)(cb + (size_t)e * C_DIM);

    float s = 0.0f;
    #pragma unroll
    for (int c4 = 0; c4 < 16; c4++) {
        float4 q = cr[c4];
        const float* zp0 = zb + (c4 * 4) * PLANE;
        float*       op0 = ob + (c4 * 4) * PLANE;
        float d;
        d = q.x - zp0[0];          s = fmaf(d, d, s); op0[0]          = q.x;
        d = q.y - zp0[PLANE];      s = fmaf(d, d, s); op0[PLANE]      = q.y;
        d = q.z - zp0[2 * PLANE];  s = fmaf(d, d, s); op0[2 * PLANE]  = q.z;
        d = q.w - zp0[3 * PLANE];  s = fmaf(d, d, s); op0[3 * PLANE]  = q.w;
    }

    out_idx_f[n] = (float)e;
    atomicAdd(&sh_hist[e], 1);

    // warp + block reduce of squared-error partial
    #pragma unroll
    for (int off = 16; off; off >>= 1) s += __shfl_xor_sync(0xffffffffu, s, off);
    if ((tid & 31) == 0) sh_red[tid >> 5] = s;
    __syncthreads();
    if (tid == 0) {
        float t = 0.0f;
        #pragma unroll
        for (int w = 0; w < 8; w++) t += sh_red[w];
        atomicAdd(&g_loss, t);
    }

    // merge histogram to global
    #pragma unroll
    for (int k = tid; k < N_E; k += 256) {
        int v = sh_hist[k];
        if (v) atomicAdd(&g_hist[k], v);
    }
}

// ---------------------------------------------------------------------------
// Kernel 3: finalize loss scalar + perplexity
// ---------------------------------------------------------------------------
__global__ void vq_finalize_kernel(float* __restrict__ out) {
    __shared__ float red[256];
    const int tid = threadIdx.x;
    float part = 0.0f;
    #pragma unroll
    for (int k = tid; k < N_E; k += 256) {
        float em = (float)g_hist[k] * (1.0f / 65536.0f);
        part += em * logf(em + 1e-10f);
    }
    red[tid] = part;
    __syncthreads();
    for (int s = 128; s; s >>= 1) {
        if (tid < s) red[tid] += red[tid + s];
        __syncthreads();
    }
    if (tid == 0) {
        out[ZQ_ELEMS]     = g_loss * (1.25f / (float)ZQ_ELEMS);  // (BETA+1)*mean
        out[ZQ_ELEMS + 1] = expf(-red[0]);                       // perplexity
    }
}

// ---------------------------------------------------------------------------
// Launch: init -> argmax -> gather -> finalize (all graph-capturable)
// Output layout: [ z_q (4194304) | loss (1) | perplexity (1) | indices (65536) ]
// ---------------------------------------------------------------------------
extern "C" void kernel_launch(void* const* d_in, const int* in_sizes, int n_in,
                              void* d_out, int out_size) {
    const float* z  = (const float*)d_in[0];
    const float* cb = (const float*)d_in[1];
    float* out = (float*)d_out;

    cudaFuncSetAttribute(vq_argmax_kernel,
                         cudaFuncAttributeMaxDynamicSharedMemorySize, 65536);

    vq_init_kernel<<<1, 256>>>();
    vq_argmax_kernel<<<N_POS / 128, 256, 65536>>>(z, cb);
    vq_gather_kernel<<<N_POS / 256, 256>>>(z, cb, out, out + ZQ_ELEMS + 2);
    vq_finalize_kernel<<<1, 256>>>(out);
    (void)in_sizes; (void)n_in; (void)out_size;
}